// round 4
// baseline (speedup 1.0000x reference)
#include <cuda_runtime.h>
#include <cfloat>
#include <cstddef>

#define B 64
#define TIN 256
#define F 64
#define H 1024
#define H3 3072
#define TGT 64
#define V 32000
#define BH (B*H)

typedef unsigned long long ULL;

__device__ float g_gi0[(size_t)TIN * B * H3];
__device__ float g_gi1[(size_t)TIN * B * H3];
__device__ float g_h0seq[(size_t)TIN * BH];
__device__ float g_enc[(size_t)TIN * BH];
__device__ float g_dh0[2 * BH];
__device__ float g_dh1[2 * BH];
__device__ float g_q[BH];
__device__ float g_cat[B * 2 * H];
__device__ float g_comb[BH];
__device__ int   g_tok[B];
__device__ unsigned long long g_bar64;

__device__ __forceinline__ void grid_sync() {
    __syncthreads();
    if (threadIdx.x == 0) {
        __threadfence();
        unsigned long long old = atomicAdd(&g_bar64, 1ULL);
        unsigned gen = (unsigned)(old >> 32);
        if ((unsigned)old == gridDim.x - 1) {
            atomicAdd(&g_bar64, (1ULL << 32) - (unsigned long long)gridDim.x);
        } else {
            while ((unsigned)((*(volatile unsigned long long*)&g_bar64) >> 32) == gen) { }
        }
        __threadfence();
    }
    __syncthreads();
}

__device__ __forceinline__ float sigmoidf_(float x) { return 1.f / (1.f + expf(-x)); }
__device__ __forceinline__ void fma2(ULL& d, ULL a, ULL b) {
    asm("fma.rn.f32x2 %0, %1, %2, %0;" : "+l"(d) : "l"(a), "l"(b));
}
__device__ __forceinline__ float2 unpack2(ULL v) {
    float2 r; asm("mov.b64 {%0, %1}, %2;" : "=f"(r.x), "=f"(r.y) : "l"(v)); return r;
}

// ============ FMA2 GEMM: C[M,N] = A[M,K] @ W[N,K]^T + bias; tile 64x128 ============
__global__ __launch_bounds__(256) void gemm2_tn(
    const float* __restrict__ A, const float* __restrict__ W,
    const float* __restrict__ bias, float* __restrict__ C,
    int K, int lda, int ldw, int ldc)
{
    __shared__ __align__(16) ULL smu2[2 * 64 * 33];
    ULL* As2 = smu2;              // [m][k] pairs {a,a}, pitch 33
    ULL* Ws2 = smu2 + 64 * 33;    // [pc][k] pairs {w_n, w_{n+16}}
    const int tid = threadIdx.x;
    const int tx = tid & 15, ty = tid >> 4;
    const int m0 = blockIdx.y * 64, n0 = blockIdx.x * 128;

    ULL acc[4][4];
#pragma unroll
    for (int r = 0; r < 4; r++)
#pragma unroll
        for (int q = 0; q < 4; q++) acc[r][q] = 0ULL;

    for (int k0 = 0; k0 < K; k0 += 32) {
        for (int i = tid; i < 2048; i += 256) {
            int m = i >> 5, k = i & 31;
            float v = A[(size_t)(m0 + m) * lda + k0 + k];
            ((float2*)As2)[m * 33 + k] = make_float2(v, v);
        }
        for (int i = tid; i < 2048; i += 256) {
            int pc = i >> 5, k = i & 31;
            int n_lo = n0 + (pc >> 4) * 32 + (pc & 15);
            ((float2*)Ws2)[pc * 33 + k] = make_float2(
                W[(size_t)n_lo * ldw + k0 + k], W[(size_t)(n_lo + 16) * ldw + k0 + k]);
        }
        __syncthreads();
#pragma unroll 8
        for (int k = 0; k < 32; k++) {
            ULL a0 = As2[ty * 33 + k], a1 = As2[(ty + 16) * 33 + k];
            ULL a2 = As2[(ty + 32) * 33 + k], a3 = As2[(ty + 48) * 33 + k];
            ULL w0 = Ws2[tx * 33 + k], w1 = Ws2[(16 + tx) * 33 + k];
            ULL w2 = Ws2[(32 + tx) * 33 + k], w3 = Ws2[(48 + tx) * 33 + k];
            fma2(acc[0][0], w0, a0); fma2(acc[0][1], w1, a0); fma2(acc[0][2], w2, a0); fma2(acc[0][3], w3, a0);
            fma2(acc[1][0], w0, a1); fma2(acc[1][1], w1, a1); fma2(acc[1][2], w2, a1); fma2(acc[1][3], w3, a1);
            fma2(acc[2][0], w0, a2); fma2(acc[2][1], w1, a2); fma2(acc[2][2], w2, a2); fma2(acc[2][3], w3, a2);
            fma2(acc[3][0], w0, a3); fma2(acc[3][1], w1, a3); fma2(acc[3][2], w2, a3); fma2(acc[3][3], w3, a3);
        }
        __syncthreads();
    }
#pragma unroll
    for (int r = 0; r < 4; r++) {
        int m = m0 + ty + 16 * r;
#pragma unroll
        for (int q = 0; q < 4; q++) {
            float2 v = unpack2(acc[r][q]);
            int n_lo = n0 + q * 32 + tx;
            C[(size_t)m * ldc + n_lo]      = v.x + bias[n_lo];
            C[(size_t)m * ldc + n_lo + 16] = v.y + bias[n_lo + 16];
        }
    }
}

// ============ persistent encoder recurrence (FMA2, weights smem-resident) ============
#define EWP 1026
#define EXP 66
__global__ __launch_bounds__(256, 1) void enc_recur_kernel(
    const float* __restrict__ gi, long long gi_t_stride, long long gi_b_stride,
    const float* __restrict__ Whh, const float* __restrict__ bhh,
    float* __restrict__ hseq)
{
    extern __shared__ __align__(16) ULL smu[];
    ULL* ws2 = smu;                 // 12 slots (gate*4+p) x EWP pairs {W[j0][k],W[j1][k]}
    ULL* xs2 = smu + 12 * EWP;      // 64 x EXP splat pairs
    const int tid = threadIdx.x;
    const int c = tid & 3, b = tid >> 2;
    const int jb = blockIdx.x * 8;
    const int j0 = jb + c, j1 = jb + c + 4;

    for (int i = tid; i < 12288; i += 256) {
        int g = i >> 12, p = (i >> 10) & 3, k = i & 1023;
        ((float2*)ws2)[(g * 4 + p) * EWP + k] = make_float2(
            Whh[(size_t)(g * H + jb + p) * H + k], Whh[(size_t)(g * H + jb + 4 + p) * H + k]);
    }
    const float br0 = bhh[j0], bz0 = bhh[H + j0], bn0 = bhh[2 * H + j0];
    const float br1 = bhh[j1], bz1 = bhh[H + j1], bn1 = bhh[2 * H + j1];
    __syncthreads();

    for (int t = 0; t < TIN; t++) {
        ULL ar = 0ULL, az = 0ULL, an = 0ULL;
        const float* hprev = hseq + (size_t)(t - 1) * BH;
        if (t > 0) {
            for (int k0 = 0; k0 < H; k0 += 64) {
                for (int i = tid; i < 4096; i += 256) {
                    int bb = i >> 6, kk = i & 63;
                    float v = hprev[(size_t)bb * H + k0 + kk];
                    ((float2*)xs2)[bb * EXP + kk] = make_float2(v, v);
                }
                __syncthreads();
                const ULL* xp = xs2 + b * EXP;
                const ULL* wr = ws2 + c * EWP + k0;
                const ULL* wz = ws2 + (4 + c) * EWP + k0;
                const ULL* wn = ws2 + (8 + c) * EWP + k0;
#pragma unroll 8
                for (int kk = 0; kk < 64; kk += 2) {
                    ulonglong2 x2 = *(const ulonglong2*)(xp + kk);
                    ulonglong2 r2 = *(const ulonglong2*)(wr + kk);
                    ulonglong2 z2 = *(const ulonglong2*)(wz + kk);
                    ulonglong2 n2 = *(const ulonglong2*)(wn + kk);
                    fma2(ar, r2.x, x2.x); fma2(az, z2.x, x2.x); fma2(an, n2.x, x2.x);
                    fma2(ar, r2.y, x2.y); fma2(az, z2.y, x2.y); fma2(an, n2.y, x2.y);
                }
                __syncthreads();
            }
        }
        const float* gr = gi + (size_t)b * gi_b_stride + (size_t)t * gi_t_stride;
        float* hout = hseq + (size_t)t * BH;
        float2 a_r = unpack2(ar), a_z = unpack2(az), a_n = unpack2(an);
        float hp0 = (t > 0) ? hprev[(size_t)b * H + j0] : 0.f;
        float hp1 = (t > 0) ? hprev[(size_t)b * H + j1] : 0.f;
        {
            float r = sigmoidf_(gr[j0] + a_r.x + br0);
            float z = sigmoidf_(gr[H + j0] + a_z.x + bz0);
            float n = tanhf(gr[2 * H + j0] + r * (a_n.x + bn0));
            hout[(size_t)b * H + j0] = (1.f - z) * n + z * hp0;
        }
        {
            float r = sigmoidf_(gr[j1] + a_r.y + br1);
            float z = sigmoidf_(gr[H + j1] + a_z.y + bz1);
            float n = tanhf(gr[2 * H + j1] + r * (a_n.y + bn1));
            hout[(size_t)b * H + j1] = (1.f - z) * n + z * hp1;
        }
        grid_sync();
    }
}

// ============ decoder (persistent): FMA2 building blocks ============
#define SMU_SZ 5016
// acc[g] (cols jb+c, jb+c+4) += sum_k W[g*H+col][k] * X[row(b)][k]
template<int NG>
__device__ __forceinline__ void block_mm2(
    const float* __restrict__ W, int wstride,
    const float* __restrict__ X, int xstride, const int* __restrict__ rowidx,
    int K, ULL* acc, ULL* smu)
{
    const int tid = threadIdx.x;
    const int c = tid & 3, b = tid >> 2;
    const int jb = blockIdx.x * 8;
    ULL* ws2 = smu;                  // NG*4 x 66
    ULL* xs2 = smu + NG * 4 * 66;    // 64 x 66

    for (int k0 = 0; k0 < K; k0 += 64) {
        for (int i = tid; i < 4096; i += 256) {
            int bb = i >> 6, kk = i & 63;
            int xr = rowidx ? rowidx[bb] : bb;
            float v = X[(size_t)xr * xstride + k0 + kk];
            ((float2*)xs2)[bb * 66 + kk] = make_float2(v, v);
        }
        for (int i = tid; i < NG * 256; i += 256) {
            int slot = i >> 6, kk = i & 63;
            int g = slot >> 2, p = slot & 3;
            ((float2*)ws2)[slot * 66 + kk] = make_float2(
                W[(size_t)(g * H + jb + p) * wstride + k0 + kk],
                W[(size_t)(g * H + jb + 4 + p) * wstride + k0 + kk]);
        }
        __syncthreads();
        const ULL* xp = xs2 + b * 66;
#pragma unroll 8
        for (int kk = 0; kk < 64; kk += 2) {
            ulonglong2 x2 = *(const ulonglong2*)(xp + kk);
#pragma unroll
            for (int g = 0; g < NG; g++) {
                ulonglong2 w2 = *(const ulonglong2*)(ws2 + (g * 4 + c) * 66 + kk);
                fma2(acc[g], w2.x, x2.x);
                fma2(acc[g], w2.y, x2.y);
            }
        }
        __syncthreads();
    }
}

__device__ __forceinline__ void dec_gru_phase(
    const float* __restrict__ x, int xstride, const int* __restrict__ rowidx,
    const float* __restrict__ Wih, const float* __restrict__ bih,
    const float* __restrict__ hin,
    const float* __restrict__ Whh, const float* __restrict__ bhh,
    float* __restrict__ hout, float* __restrict__ cat_aux, ULL* smu)
{
    if (blockIdx.x < 128) {
        ULL ai[3] = {0,0,0}, ah[3] = {0,0,0};
        block_mm2<3>(Wih, H, x, xstride, rowidx, H, ai, smu);
        block_mm2<3>(Whh, H, hin, H, nullptr, H, ah, smu);
        const int tid = threadIdx.x, c = tid & 3, b = tid >> 2;
        const int jb = blockIdx.x * 8;
        float2 air = unpack2(ai[0]), aiz = unpack2(ai[1]), ain = unpack2(ai[2]);
        float2 ahr = unpack2(ah[0]), ahz = unpack2(ah[1]), ahn = unpack2(ah[2]);
#pragma unroll
        for (int u = 0; u < 2; u++) {
            int j = jb + c + 4 * u;
            float aiu_r = u ? air.y : air.x, aiu_z = u ? aiz.y : aiz.x, aiu_n = u ? ain.y : ain.x;
            float ahu_r = u ? ahr.y : ahr.x, ahu_z = u ? ahz.y : ahz.x, ahu_n = u ? ahn.y : ahn.x;
            float hp = hin[(size_t)b * H + j];
            float r = sigmoidf_((aiu_r + bih[j]) + (ahu_r + bhh[j]));
            float z = sigmoidf_((aiu_z + bih[H + j]) + (ahu_z + bhh[H + j]));
            float n = tanhf((aiu_n + bih[2 * H + j]) + r * (ahu_n + bhh[2 * H + j]));
            float h = (1.f - z) * n + z * hp;
            hout[(size_t)b * H + j] = h;
            if (cat_aux) cat_aux[(size_t)b * 2 * H + H + j] = h;
        }
    }
    grid_sync();
}

__device__ __forceinline__ void lin_phase(
    const float* __restrict__ Wt, int wstride, const float* __restrict__ bias,
    const float* __restrict__ X, int xstride, int K, float* __restrict__ Y, ULL* smu)
{
    if (blockIdx.x < 128) {
        ULL a[1] = {0ULL};
        block_mm2<1>(Wt, wstride, X, xstride, nullptr, K, a, smu);
        const int tid = threadIdx.x, c = tid & 3, b = tid >> 2;
        const int jb = blockIdx.x * 8;
        float2 v = unpack2(a[0]);
        Y[(size_t)b * H + jb + c]     = v.x + bias[jb + c];
        Y[(size_t)b * H + jb + c + 4] = v.y + bias[jb + c + 4];
    }
    grid_sync();
}

__device__ __forceinline__ void attn_phase(
    const float* __restrict__ q, const float* __restrict__ enc,
    float* __restrict__ cat, float* __restrict__ attn_out, int s, float* sm)
{
    if (blockIdx.x < B) {
        const int b = blockIdx.x, tid = threadIdx.x;
        float* qs = sm;
        float* wv = sm + 1024;
        float* red = sm + 1280;
        for (int i = tid; i < H; i += 256) qs[i] = q[(size_t)b * H + i];
        __syncthreads();
        const int warp = tid >> 5, lane = tid & 31;
        for (int t = warp; t < TIN; t += 8) {
            const float* e = enc + (size_t)(t * B + b) * H;
            float sacc = 0.f;
#pragma unroll 4
            for (int k = lane; k < H; k += 32) sacc = fmaf(qs[k], e[k], sacc);
            for (int o = 16; o; o >>= 1) sacc += __shfl_xor_sync(0xffffffffu, sacc, o);
            if (!lane) wv[t] = sacc;
        }
        __syncthreads();
        float v = wv[tid];
        red[tid] = v; __syncthreads();
        for (int st = 128; st; st >>= 1) { if (tid < st) red[tid] = fmaxf(red[tid], red[tid + st]); __syncthreads(); }
        float mx = red[0]; __syncthreads();
        float ev = expf(v - mx);
        red[tid] = ev; __syncthreads();
        for (int st = 128; st; st >>= 1) { if (tid < st) red[tid] += red[tid + st]; __syncthreads(); }
        float aw = ev / red[0];
        wv[tid] = aw;
        attn_out[((size_t)b * TIN + tid) * TGT + s] = aw;
        __syncthreads();
#pragma unroll
        for (int kk = 0; kk < 4; kk++) {
            int k = tid + kk * 256;
            float sacc = 0.f;
            for (int t = 0; t < TIN; t++) sacc = fmaf(wv[t], enc[(size_t)(t * B + b) * H + k], sacc);
            cat[(size_t)b * 2 * H + k] = sacc;
        }
    }
    grid_sync();
}

__device__ __forceinline__ void fc_phase(
    const float* __restrict__ A, const float* __restrict__ Wfc,
    const float* __restrict__ bfc, float* __restrict__ out, int s, ULL* smu)
{
    ULL* As2 = smu;             // 64 x 33 splat pairs
    ULL* Ws2 = smu + 2112;      // 64 x 33 col pairs (n, n+16)
    const int tid = threadIdx.x;
    const int tx = tid & 15, ty = tid >> 4;
    for (int tile = blockIdx.x; tile < V / 128; tile += gridDim.x) {
        const int n0 = tile * 128;
        ULL acc[4][4];
#pragma unroll
        for (int r = 0; r < 4; r++)
#pragma unroll
            for (int q = 0; q < 4; q++) acc[r][q] = 0ULL;
        for (int k0 = 0; k0 < H; k0 += 32) {
            for (int i = tid; i < 2048; i += 256) {
                int m = i >> 5, k = i & 31;
                float v = A[(size_t)m * H + k0 + k];
                ((float2*)As2)[m * 33 + k] = make_float2(v, v);
            }
            for (int i = tid; i < 2048; i += 256) {
                int pc = i >> 5, k = i & 31;
                int n_lo = n0 + (pc >> 4) * 32 + (pc & 15);
                ((float2*)Ws2)[pc * 33 + k] = make_float2(
                    Wfc[(size_t)n_lo * H + k0 + k], Wfc[(size_t)(n_lo + 16) * H + k0 + k]);
            }
            __syncthreads();
#pragma unroll 8
            for (int k = 0; k < 32; k++) {
                ULL a0 = As2[ty * 33 + k], a1 = As2[(ty + 16) * 33 + k];
                ULL a2 = As2[(ty + 32) * 33 + k], a3 = As2[(ty + 48) * 33 + k];
                ULL w0 = Ws2[tx * 33 + k], w1 = Ws2[(16 + tx) * 33 + k];
                ULL w2 = Ws2[(32 + tx) * 33 + k], w3 = Ws2[(48 + tx) * 33 + k];
                fma2(acc[0][0], w0, a0); fma2(acc[0][1], w1, a0); fma2(acc[0][2], w2, a0); fma2(acc[0][3], w3, a0);
                fma2(acc[1][0], w0, a1); fma2(acc[1][1], w1, a1); fma2(acc[1][2], w2, a1); fma2(acc[1][3], w3, a1);
                fma2(acc[2][0], w0, a2); fma2(acc[2][1], w1, a2); fma2(acc[2][2], w2, a2); fma2(acc[2][3], w3, a2);
                fma2(acc[3][0], w0, a3); fma2(acc[3][1], w1, a3); fma2(acc[3][2], w2, a3); fma2(acc[3][3], w3, a3);
            }
            __syncthreads();
        }
#pragma unroll
        for (int r = 0; r < 4; r++) {
            int m = ty + 16 * r;
#pragma unroll
            for (int q = 0; q < 4; q++) {
                float2 v = unpack2(acc[r][q]);
                int n_lo = n0 + q * 32 + tx;
                out[((size_t)m * TGT + s) * V + n_lo]      = v.x + bfc[n_lo];
                out[((size_t)m * TGT + s) * V + n_lo + 16] = v.y + bfc[n_lo + 16];
            }
        }
    }
    grid_sync();
}

__device__ __forceinline__ void argmax_phase(const float* __restrict__ out, int s, float* sm)
{
    if (blockIdx.x < B) {
        const int b = blockIdx.x, tid = threadIdx.x;
        const float* row = out + ((size_t)b * TGT + s) * V;
        float best = -FLT_MAX; int bi = 0;
        for (int i = tid; i < V; i += 256) {
            float x = row[i];
            if (x > best) { best = x; bi = i; }
        }
        float* sv = sm;
        int* si = (int*)(sm + 256);
        sv[tid] = best; si[tid] = bi; __syncthreads();
        for (int st = 128; st; st >>= 1) {
            if (tid < st) {
                if (sv[tid + st] > sv[tid] ||
                    (sv[tid + st] == sv[tid] && si[tid + st] < si[tid])) {
                    sv[tid] = sv[tid + st]; si[tid] = si[tid + st];
                }
            }
            __syncthreads();
        }
        if (!tid) g_tok[b] = si[0];
    }
    grid_sync();
}

__global__ __launch_bounds__(256, 1) void decoder_kernel(
    const float* __restrict__ embed,
    const float* __restrict__ dWih0, const float* __restrict__ dbih0,
    const float* __restrict__ dWhh0, const float* __restrict__ dbhh0,
    const float* __restrict__ dWih1, const float* __restrict__ dbih1,
    const float* __restrict__ dWhh1, const float* __restrict__ dbhh1,
    const float* __restrict__ Wq, const float* __restrict__ bq,
    const float* __restrict__ Wc, const float* __restrict__ bc,
    const float* __restrict__ Wfc, const float* __restrict__ bfc,
    float* __restrict__ out)
{
    __shared__ __align__(16) ULL smu[SMU_SZ];
    __shared__ int toks[B];
    const size_t HID_OFF = (size_t)B * TGT * V;
    const size_t ATTN_OFF = HID_OFF + (size_t)2 * BH;

    for (int s = 0; s < TGT; s++) {
        if (threadIdx.x < B) toks[threadIdx.x] = s ? g_tok[threadIdx.x] : 0;
        __syncthreads();
        const float* h0in = s ? (g_dh0 + (size_t)((s - 1) & 1) * BH) : (g_h0seq + (size_t)(TIN - 1) * BH);
        const float* h1in = s ? (g_dh1 + (size_t)((s - 1) & 1) * BH) : (g_enc + (size_t)(TIN - 1) * BH);
        float* h0out = g_dh0 + (size_t)(s & 1) * BH;
        float* h1out = g_dh1 + (size_t)(s & 1) * BH;

        dec_gru_phase(embed, H, toks, dWih0, dbih0, h0in, dWhh0, dbhh0, h0out, nullptr, smu);
        dec_gru_phase(h0out, H, nullptr, dWih1, dbih1, h1in, dWhh1, dbhh1, h1out, g_cat, smu);
        lin_phase(Wq, H, bq, h1out, H, H, g_q, smu);
        attn_phase(g_q, g_enc, g_cat, out + ATTN_OFF, s, (float*)smu);
        lin_phase(Wc, 2 * H, bc, g_cat, 2 * H, 2 * H, g_comb, smu);
        fc_phase(g_comb, Wfc, bfc, out, s, smu);
        argmax_phase(out, s, (float*)smu);
    }
    const float* f0 = g_dh0 + (size_t)((TGT - 1) & 1) * BH;
    const float* f1 = g_dh1 + (size_t)((TGT - 1) & 1) * BH;
    for (size_t i = (size_t)blockIdx.x * 256 + threadIdx.x; i < (size_t)BH;
         i += (size_t)gridDim.x * 256) {
        out[HID_OFF + i] = f0[i];
        out[HID_OFF + BH + i] = f1[i];
    }
}

extern "C" void kernel_launch(void* const* d_in, const int* in_sizes, int n_in,
                              void* d_out_, int out_size) {
    const float* x      = (const float*)d_in[0];
    const float* embed  = (const float*)d_in[1];
    const float* eWih0  = (const float*)d_in[2];
    const float* eWhh0  = (const float*)d_in[3];
    const float* ebih0  = (const float*)d_in[4];
    const float* ebhh0  = (const float*)d_in[5];
    const float* eWih1  = (const float*)d_in[6];
    const float* eWhh1  = (const float*)d_in[7];
    const float* ebih1  = (const float*)d_in[8];
    const float* ebhh1  = (const float*)d_in[9];
    const float* dWih0  = (const float*)d_in[10];
    const float* dWhh0  = (const float*)d_in[11];
    const float* dbih0  = (const float*)d_in[12];
    const float* dbhh0  = (const float*)d_in[13];
    const float* dWih1  = (const float*)d_in[14];
    const float* dWhh1  = (const float*)d_in[15];
    const float* dbih1  = (const float*)d_in[16];
    const float* dbhh1  = (const float*)d_in[17];
    const float* Wq     = (const float*)d_in[18];
    const float* bq     = (const float*)d_in[19];
    const float* Wc     = (const float*)d_in[20];
    const float* bc     = (const float*)d_in[21];
    const float* Wfc    = (const float*)d_in[22];
    const float* bfc    = (const float*)d_in[23];
    float* out = (float*)d_out_;

    float *gi0, *gi1, *h0seq, *enc;
    cudaGetSymbolAddress((void**)&gi0,   g_gi0);
    cudaGetSymbolAddress((void**)&gi1,   g_gi1);
    cudaGetSymbolAddress((void**)&h0seq, g_h0seq);
    cudaGetSymbolAddress((void**)&enc,   g_enc);

    const int ENC_SMEM = (12 * EWP + 64 * EXP) * (int)sizeof(ULL);   // 132,288 B
    cudaFuncSetAttribute(enc_recur_kernel, cudaFuncAttributeMaxDynamicSharedMemorySize, ENC_SMEM);

    int dev = 0; cudaGetDevice(&dev);
    int nb = 0;
    cudaDeviceGetAttribute(&nb, cudaDevAttrMultiProcessorCount, dev);
    if (nb < 128) nb = 148;

    // 1) gi0 = X @ eWih0^T + ebih0  (rows b*TIN+t, K=F)
    gemm2_tn<<<dim3(H3/128, (B*TIN)/64), 256>>>(x, eWih0, ebih0, gi0, F, F, F, H3);
    // 2) encoder layer 0 recurrence
    enc_recur_kernel<<<128, 256, ENC_SMEM>>>(
        gi0, (long long)H3, (long long)TIN * H3, eWhh0, ebhh0, h0seq);
    // 3) gi1 = H0seq @ eWih1^T + ebih1  (rows t*B+b, K=H)
    gemm2_tn<<<dim3(H3/128, (B*TIN)/64), 256>>>(h0seq, eWih1, ebih1, gi1, H, H, H, H3);
    // 4) encoder layer 1 recurrence
    enc_recur_kernel<<<128, 256, ENC_SMEM>>>(
        gi1, (long long)B * H3, (long long)H3, eWhh1, ebhh1, enc);
    // 5) full autoregressive decoder
    decoder_kernel<<<nb, 256>>>(
        embed, dWih0, dbih0, dWhh0, dbhh0, dWih1, dbih1, dWhh1, dbhh1,
        Wq, bq, Wc, bc, Wfc, bfc, out);
}

// round 5
// speedup vs baseline: 1.3908x; 1.3908x over previous
#include <cuda_runtime.h>
#include <cfloat>
#include <cstddef>

#define B 64
#define TIN 256
#define F 64
#define H 1024
#define H3 3072
#define TGT 64
#define V 32000
#define BH (B*H)

typedef unsigned long long ULL;

__device__ float g_gi0[(size_t)TIN * B * H3];
__device__ float g_gi1[(size_t)TIN * B * H3];
__device__ float g_h0seq[(size_t)TIN * BH];
__device__ float g_enc[(size_t)TIN * BH];
__device__ float g_dh0[2 * BH];
__device__ float g_dh1[2 * BH];
__device__ float g_q[BH];
__device__ float g_cat[B * 2 * H];
__device__ float g_comb[BH];
__device__ int   g_tok[B];
__device__ unsigned long long g_bar64;

__device__ __forceinline__ void grid_sync() {
    __syncthreads();
    if (threadIdx.x == 0) {
        __threadfence();
        unsigned long long old = atomicAdd(&g_bar64, 1ULL);
        unsigned gen = (unsigned)(old >> 32);
        if ((unsigned)old == gridDim.x - 1) {
            atomicAdd(&g_bar64, (1ULL << 32) - (unsigned long long)gridDim.x);
        } else {
            while ((unsigned)((*(volatile unsigned long long*)&g_bar64) >> 32) == gen) { }
        }
        __threadfence();
    }
    __syncthreads();
}

__device__ __forceinline__ float sigmoidf_(float x) { return 1.f / (1.f + expf(-x)); }
__device__ __forceinline__ void fma2(ULL& d, ULL a, ULL b) {
    asm("fma.rn.f32x2 %0, %1, %2, %0;" : "+l"(d) : "l"(a), "l"(b));
}
__device__ __forceinline__ float2 unpack2(ULL v) {
    float2 r; asm("mov.b64 {%0, %1}, %2;" : "=f"(r.x), "=f"(r.y) : "l"(v)); return r;
}

// ============ FMA2 GEMM (bitwise-proven in R4): C = A @ W^T + bias, tile 64x128 ============
__global__ __launch_bounds__(256) void gemm2_tn(
    const float* __restrict__ A, const float* __restrict__ W,
    const float* __restrict__ bias, float* __restrict__ C,
    int K, int lda, int ldw, int ldc)
{
    __shared__ __align__(16) ULL smu2[2 * 64 * 33];
    ULL* As2 = smu2;
    ULL* Ws2 = smu2 + 64 * 33;
    const int tid = threadIdx.x;
    const int tx = tid & 15, ty = tid >> 4;
    const int m0 = blockIdx.y * 64, n0 = blockIdx.x * 128;

    ULL acc[4][4];
#pragma unroll
    for (int r = 0; r < 4; r++)
#pragma unroll
        for (int q = 0; q < 4; q++) acc[r][q] = 0ULL;

    for (int k0 = 0; k0 < K; k0 += 32) {
        for (int i = tid; i < 2048; i += 256) {
            int m = i >> 5, k = i & 31;
            float v = A[(size_t)(m0 + m) * lda + k0 + k];
            ((float2*)As2)[m * 33 + k] = make_float2(v, v);
        }
        for (int i = tid; i < 2048; i += 256) {
            int pc = i >> 5, k = i & 31;
            int n_lo = n0 + (pc >> 4) * 32 + (pc & 15);
            ((float2*)Ws2)[pc * 33 + k] = make_float2(
                W[(size_t)n_lo * ldw + k0 + k], W[(size_t)(n_lo + 16) * ldw + k0 + k]);
        }
        __syncthreads();
#pragma unroll 8
        for (int k = 0; k < 32; k++) {
            ULL a0 = As2[ty * 33 + k], a1 = As2[(ty + 16) * 33 + k];
            ULL a2 = As2[(ty + 32) * 33 + k], a3 = As2[(ty + 48) * 33 + k];
            ULL w0 = Ws2[tx * 33 + k], w1 = Ws2[(16 + tx) * 33 + k];
            ULL w2 = Ws2[(32 + tx) * 33 + k], w3 = Ws2[(48 + tx) * 33 + k];
            fma2(acc[0][0], w0, a0); fma2(acc[0][1], w1, a0); fma2(acc[0][2], w2, a0); fma2(acc[0][3], w3, a0);
            fma2(acc[1][0], w0, a1); fma2(acc[1][1], w1, a1); fma2(acc[1][2], w2, a1); fma2(acc[1][3], w3, a1);
            fma2(acc[2][0], w0, a2); fma2(acc[2][1], w1, a2); fma2(acc[2][2], w2, a2); fma2(acc[2][3], w3, a2);
            fma2(acc[3][0], w0, a3); fma2(acc[3][1], w1, a3); fma2(acc[3][2], w2, a3); fma2(acc[3][3], w3, a3);
        }
        __syncthreads();
    }
#pragma unroll
    for (int r = 0; r < 4; r++) {
        int m = m0 + ty + 16 * r;
#pragma unroll
        for (int q = 0; q < 4; q++) {
            float2 v = unpack2(acc[r][q]);
            int n_lo = n0 + q * 32 + tx;
            C[(size_t)m * ldc + n_lo]      = v.x + bias[n_lo];
            C[(size_t)m * ldc + n_lo + 16] = v.y + bias[n_lo + 16];
        }
    }
}

// ============ persistent encoder recurrence — R2 version verbatim (60% of fp32 peak) ============
#define WS_PITCH 1028
#define XS_PITCH 68
__global__ __launch_bounds__(256, 1) void enc_recur_kernel(
    const float* __restrict__ gi, long long gi_t_stride, long long gi_b_stride,
    const float* __restrict__ Whh, const float* __restrict__ bhh,
    float* __restrict__ hseq)
{
    extern __shared__ float sm[];
    float* ws = sm;
    float* xs = sm + 24 * WS_PITCH;

    const int tid = threadIdx.x;
    const int c = tid & 7, bq = tid >> 3;
    const int jb = blockIdx.x * 8;
    const int b0 = 2 * bq, b1 = b0 + 1;
    const int j = jb + c;

    for (int i = tid; i < 24 * 256; i += 256) {
        int r = i >> 8, kg = i & 255;
        int wr = (r >> 3) * H + jb + (r & 7);
        *(float4*)(ws + r * WS_PITCH + kg * 4) =
            *(const float4*)(Whh + (size_t)wr * H + kg * 4);
    }
    const float br = bhh[j], bz = bhh[H + j], bn = bhh[2 * H + j];
    __syncthreads();

    for (int t = 0; t < TIN; t++) {
        float ar0 = 0.f, ar1 = 0.f, az0 = 0.f, az1 = 0.f, an0 = 0.f, an1 = 0.f;
        const float* hprev = hseq + (size_t)(t - 1) * BH;
        if (t > 0) {
            for (int k0 = 0; k0 < H; k0 += 64) {
                for (int i = tid; i < 1024; i += 256) {
                    int b = i >> 4, kg = i & 15;
                    *(float4*)(xs + b * XS_PITCH + kg * 4) =
                        *(const float4*)(hprev + (size_t)b * H + k0 + kg * 4);
                }
                __syncthreads();
#pragma unroll
                for (int kk = 0; kk < 64; kk += 4) {
                    float4 x0 = *(const float4*)(xs + b0 * XS_PITCH + kk);
                    float4 x1 = *(const float4*)(xs + b1 * XS_PITCH + kk);
                    float4 w0 = *(const float4*)(ws + c * WS_PITCH + k0 + kk);
                    float4 w1 = *(const float4*)(ws + (8 + c) * WS_PITCH + k0 + kk);
                    float4 w2 = *(const float4*)(ws + (16 + c) * WS_PITCH + k0 + kk);
                    ar0 = fmaf(w0.x, x0.x, ar0); ar0 = fmaf(w0.y, x0.y, ar0);
                    ar0 = fmaf(w0.z, x0.z, ar0); ar0 = fmaf(w0.w, x0.w, ar0);
                    ar1 = fmaf(w0.x, x1.x, ar1); ar1 = fmaf(w0.y, x1.y, ar1);
                    ar1 = fmaf(w0.z, x1.z, ar1); ar1 = fmaf(w0.w, x1.w, ar1);
                    az0 = fmaf(w1.x, x0.x, az0); az0 = fmaf(w1.y, x0.y, az0);
                    az0 = fmaf(w1.z, x0.z, az0); az0 = fmaf(w1.w, x0.w, az0);
                    az1 = fmaf(w1.x, x1.x, az1); az1 = fmaf(w1.y, x1.y, az1);
                    az1 = fmaf(w1.z, x1.z, az1); az1 = fmaf(w1.w, x1.w, az1);
                    an0 = fmaf(w2.x, x0.x, an0); an0 = fmaf(w2.y, x0.y, an0);
                    an0 = fmaf(w2.z, x0.z, an0); an0 = fmaf(w2.w, x0.w, an0);
                    an1 = fmaf(w2.x, x1.x, an1); an1 = fmaf(w2.y, x1.y, an1);
                    an1 = fmaf(w2.z, x1.z, an1); an1 = fmaf(w2.w, x1.w, an1);
                }
                __syncthreads();
            }
        }
        const float* gr0 = gi + (size_t)b0 * gi_b_stride + (size_t)t * gi_t_stride;
        const float* gr1 = gi + (size_t)b1 * gi_b_stride + (size_t)t * gi_t_stride;
        float* hout = hseq + (size_t)t * BH;
        float hp0 = (t > 0) ? hprev[(size_t)b0 * H + j] : 0.f;
        float hp1 = (t > 0) ? hprev[(size_t)b1 * H + j] : 0.f;
        {
            float r = sigmoidf_(gr0[j] + ar0 + br);
            float z = sigmoidf_(gr0[H + j] + az0 + bz);
            float n = tanhf(gr0[2 * H + j] + r * (an0 + bn));
            hout[(size_t)b0 * H + j] = (1.f - z) * n + z * hp0;
        }
        {
            float r = sigmoidf_(gr1[j] + ar1 + br);
            float z = sigmoidf_(gr1[H + j] + az1 + bz);
            float n = tanhf(gr1[2 * H + j] + r * (an1 + bn));
            hout[(size_t)b1 * H + j] = (1.f - z) * n + z * hp1;
        }
        grid_sync();
    }
}

// ================== decoder: 128 blocks x 1024 threads, dynamic smem ==================
// dynamic smem layout (ULL units):
#define WS_IH 0            // 12*66 = 792
#define WS_HH 792          // 792
#define XS_X  1584         // 64*66 = 4224
#define XS_H  5808         // 4224   (total 10032 ULL = 80256 B)
#define PM    1584         // 6*256 partials, overlaps XS_X (used after final chunk sync)
#define DSM_ULL 10032

// GRU: 6 whole chains (ai_r,ai_z,ai_n,ah_r,ah_z,ah_n) split across 4 thread groups.
__device__ void dec_gru_1024(
    const float* __restrict__ x, int xstride, const int* __restrict__ toks,
    const float* __restrict__ Wih, const float* __restrict__ bih,
    const float* __restrict__ hin,
    const float* __restrict__ Whh, const float* __restrict__ bhh,
    float* __restrict__ hout, float* __restrict__ cat_aux, ULL* smu)
{
    const int tid = threadIdx.x;
    const int idx = tid & 255;
    const int c = idx & 3, b = idx >> 2;
    const int grp = tid >> 8;
    const int jb = blockIdx.x * 8;
    ULL a0 = 0ULL, a1 = 0ULL;

    ULL* wsI = smu + WS_IH;
    ULL* wsH = smu + WS_HH;
    ULL* xsX = smu + XS_X;
    ULL* xsH = smu + XS_H;

    for (int k0 = 0; k0 < H; k0 += 64) {
        for (int i = tid; i < 4096; i += 1024) {
            int bb = i >> 6, kk = i & 63;
            int xr = toks ? toks[bb] : bb;
            float v = x[(size_t)xr * xstride + k0 + kk];
            ((float2*)xsX)[bb * 66 + kk] = make_float2(v, v);
            float h = hin[(size_t)bb * H + k0 + kk];
            ((float2*)xsH)[bb * 66 + kk] = make_float2(h, h);
        }
        for (int i = tid; i < 768; i += 1024) {
            int slot = i >> 6, kk = i & 63;
            int g = slot >> 2, p = slot & 3;
            ((float2*)wsI)[slot * 66 + kk] = make_float2(
                Wih[(size_t)(g * H + jb + p) * H + k0 + kk],
                Wih[(size_t)(g * H + jb + 4 + p) * H + k0 + kk]);
            ((float2*)wsH)[slot * 66 + kk] = make_float2(
                Whh[(size_t)(g * H + jb + p) * H + k0 + kk],
                Whh[(size_t)(g * H + jb + 4 + p) * H + k0 + kk]);
        }
        __syncthreads();
        const ULL* xp = ((grp & 2) ? xsH : xsX) + b * 66;
        const ULL* ws = (grp & 2) ? wsH : wsI;
        if (!(grp & 1)) {
            const ULL* wr = ws + c * 66;
            const ULL* wz = ws + (4 + c) * 66;
#pragma unroll 8
            for (int kk = 0; kk < 64; kk += 2) {
                ulonglong2 x2 = *(const ulonglong2*)(xp + kk);
                ulonglong2 r2 = *(const ulonglong2*)(wr + kk);
                ulonglong2 z2 = *(const ulonglong2*)(wz + kk);
                fma2(a0, r2.x, x2.x); fma2(a1, z2.x, x2.x);
                fma2(a0, r2.y, x2.y); fma2(a1, z2.y, x2.y);
            }
        } else {
            const ULL* wn = ws + (8 + c) * 66;
#pragma unroll 8
            for (int kk = 0; kk < 64; kk += 2) {
                ulonglong2 x2 = *(const ulonglong2*)(xp + kk);
                ulonglong2 n2 = *(const ulonglong2*)(wn + kk);
                fma2(a0, n2.x, x2.x);
                fma2(a0, n2.y, x2.y);
            }
        }
        __syncthreads();
    }
    ULL* pm = smu + PM;
    if (grp == 0)      { pm[idx] = a0; pm[256 + idx] = a1; }
    else if (grp == 1) { pm[512 + idx] = a0; }
    else if (grp == 2) { pm[768 + idx] = a0; pm[1024 + idx] = a1; }
    else               { pm[1280 + idx] = a0; }
    __syncthreads();
    if (grp == 0) {
        float2 air = unpack2(pm[idx]),        aiz = unpack2(pm[256 + idx]),  ain = unpack2(pm[512 + idx]);
        float2 ahr = unpack2(pm[768 + idx]),  ahz = unpack2(pm[1024 + idx]), ahn = unpack2(pm[1280 + idx]);
#pragma unroll
        for (int u = 0; u < 2; u++) {
            int j = jb + c + 4 * u;
            float aiu_r = u ? air.y : air.x, aiu_z = u ? aiz.y : aiz.x, aiu_n = u ? ain.y : ain.x;
            float ahu_r = u ? ahr.y : ahr.x, ahu_z = u ? ahz.y : ahz.x, ahu_n = u ? ahn.y : ahn.x;
            float hp = hin[(size_t)b * H + j];
            float r = sigmoidf_((aiu_r + bih[j]) + (ahu_r + bhh[j]));
            float z = sigmoidf_((aiu_z + bih[H + j]) + (ahu_z + bhh[H + j]));
            float n = tanhf((aiu_n + bih[2 * H + j]) + r * (ahu_n + bhh[2 * H + j]));
            float h = (1.f - z) * n + z * hp;
            hout[(size_t)b * H + j] = h;
            if (cat_aux) cat_aux[(size_t)b * 2 * H + H + j] = h;
        }
    }
}

__device__ void lin_1024(
    const float* __restrict__ Wt, int wstride, const float* __restrict__ bias,
    const float* __restrict__ X, int xstride, int K, float* __restrict__ Y, ULL* smu)
{
    const int tid = threadIdx.x;
    const int idx = tid & 255;
    const int c = idx & 3, b = idx >> 2;
    const int grp = tid >> 8;
    const int jb = blockIdx.x * 8;
    ULL a0 = 0ULL;
    ULL* ws = smu;            // 4 x 66
    ULL* xs = smu + 264;      // 64 x 66

    for (int k0 = 0; k0 < K; k0 += 64) {
        for (int i = tid; i < 4096; i += 1024) {
            int bb = i >> 6, kk = i & 63;
            float v = X[(size_t)bb * xstride + k0 + kk];
            ((float2*)xs)[bb * 66 + kk] = make_float2(v, v);
        }
        if (tid < 256) {
            int p = tid >> 6, kk = tid & 63;
            ((float2*)ws)[p * 66 + kk] = make_float2(
                Wt[(size_t)(jb + p) * wstride + k0 + kk],
                Wt[(size_t)(jb + 4 + p) * wstride + k0 + kk]);
        }
        __syncthreads();
        if (grp == 0) {
            const ULL* xp = xs + b * 66;
            const ULL* wp = ws + c * 66;
#pragma unroll 8
            for (int kk = 0; kk < 64; kk += 2) {
                ulonglong2 x2 = *(const ulonglong2*)(xp + kk);
                ulonglong2 w2 = *(const ulonglong2*)(wp + kk);
                fma2(a0, w2.x, x2.x);
                fma2(a0, w2.y, x2.y);
            }
        }
        __syncthreads();
    }
    if (grp == 0) {
        float2 v = unpack2(a0);
        Y[(size_t)b * H + jb + c]     = v.x + bias[jb + c];
        Y[(size_t)b * H + jb + c + 4] = v.y + bias[jb + c + 4];
    }
}

__device__ void attn_1024(
    const float* __restrict__ q, const float* __restrict__ enc,
    float* __restrict__ cat, float* __restrict__ attn_out, int s, float* sm)
{
    if (blockIdx.x < B) {
        const int b = blockIdx.x, tid = threadIdx.x;
        float* qs = sm;
        float* wv = sm + 1024;
        float* red = sm + 1280;
        qs[tid] = q[(size_t)b * H + tid];
        __syncthreads();
        const int warp = tid >> 5, lane = tid & 31;
        for (int t = warp; t < TIN; t += 32) {
            const float* e = enc + (size_t)(t * B + b) * H;
            float sacc = 0.f;
#pragma unroll 4
            for (int k = lane; k < H; k += 32) sacc = fmaf(qs[k], e[k], sacc);
            for (int o = 16; o; o >>= 1) sacc += __shfl_xor_sync(0xffffffffu, sacc, o);
            if (!lane) wv[t] = sacc;
        }
        __syncthreads();
        float v = 0.f, ev = 0.f;
        if (tid < 256) { v = wv[tid]; red[tid] = v; }
        __syncthreads();
        for (int st = 128; st; st >>= 1) { if (tid < st) red[tid] = fmaxf(red[tid], red[tid + st]); __syncthreads(); }
        float mx = red[0]; __syncthreads();
        if (tid < 256) { ev = expf(v - mx); red[tid] = ev; }
        __syncthreads();
        for (int st = 128; st; st >>= 1) { if (tid < st) red[tid] += red[tid + st]; __syncthreads(); }
        if (tid < 256) {
            float aw = ev / red[0];
            wv[tid] = aw;
            attn_out[((size_t)b * TIN + tid) * TGT + s] = aw;
        }
        __syncthreads();
        {
            int k = tid;
            float sacc = 0.f;
            for (int t = 0; t < TIN; t++) sacc = fmaf(wv[t], enc[(size_t)(t * B + b) * H + k], sacc);
            cat[(size_t)b * 2 * H + k] = sacc;
        }
    }
}

__device__ void fc_1024(
    const float* __restrict__ A, const float* __restrict__ Wfc,
    const float* __restrict__ bfc, float* __restrict__ out, int s, ULL* smu)
{
    if (blockIdx.x < V / 256) {
        ULL* As2 = smu;           // 64 x 33
        ULL* Ws2 = smu + 2112;    // 128 x 33
        const int tid = threadIdx.x;
        const int tx = tid & 31, ty = tid >> 5;
        const int n0 = blockIdx.x * 256;
        ULL acc[2][4];
#pragma unroll
        for (int r = 0; r < 2; r++)
#pragma unroll
            for (int q = 0; q < 4; q++) acc[r][q] = 0ULL;
        for (int k0 = 0; k0 < H; k0 += 32) {
            for (int i = tid; i < 2048; i += 1024) {
                int m = i >> 5, k = i & 31;
                float v = A[(size_t)m * H + k0 + k];
                ((float2*)As2)[m * 33 + k] = make_float2(v, v);
            }
            for (int i = tid; i < 4096; i += 1024) {
                int pc = i >> 5, k = i & 31;
                int n_lo = n0 + (pc >> 4) * 32 + (pc & 15);
                ((float2*)Ws2)[pc * 33 + k] = make_float2(
                    Wfc[(size_t)n_lo * H + k0 + k], Wfc[(size_t)(n_lo + 16) * H + k0 + k]);
            }
            __syncthreads();
#pragma unroll 8
            for (int k = 0; k < 32; k++) {
                ULL a0 = As2[ty * 33 + k], a1 = As2[(ty + 32) * 33 + k];
                ULL w0 = Ws2[tx * 33 + k],        w1 = Ws2[(tx + 32) * 33 + k];
                ULL w2 = Ws2[(tx + 64) * 33 + k], w3 = Ws2[(tx + 96) * 33 + k];
                fma2(acc[0][0], w0, a0); fma2(acc[0][1], w1, a0);
                fma2(acc[0][2], w2, a0); fma2(acc[0][3], w3, a0);
                fma2(acc[1][0], w0, a1); fma2(acc[1][1], w1, a1);
                fma2(acc[1][2], w2, a1); fma2(acc[1][3], w3, a1);
            }
            __syncthreads();
        }
#pragma unroll
        for (int r = 0; r < 2; r++) {
            int m = ty + 32 * r;
#pragma unroll
            for (int q = 0; q < 4; q++) {
                int pc = tx + 32 * q;
                int n_lo = n0 + (pc >> 4) * 32 + (pc & 15);
                float2 v = unpack2(acc[r][q]);
                out[((size_t)m * TGT + s) * V + n_lo]      = v.x + bfc[n_lo];
                out[((size_t)m * TGT + s) * V + n_lo + 16] = v.y + bfc[n_lo + 16];
            }
        }
    }
}

__device__ void argmax_1024(const float* __restrict__ out, int s, float* sm)
{
    if (blockIdx.x < B) {
        const int b = blockIdx.x, tid = threadIdx.x;
        const float* row = out + ((size_t)b * TGT + s) * V;
        float best = -FLT_MAX; int bi = 0;
        for (int i = tid; i < V; i += 1024) {
            float x = row[i];
            if (x > best) { best = x; bi = i; }
        }
        float* sv = sm;
        int* si = (int*)(sm + 1024);
        sv[tid] = best; si[tid] = bi; __syncthreads();
        for (int st = 512; st; st >>= 1) {
            if (tid < st) {
                if (sv[tid + st] > sv[tid] ||
                    (sv[tid + st] == sv[tid] && si[tid + st] < si[tid])) {
                    sv[tid] = sv[tid + st]; si[tid] = si[tid + st];
                }
            }
            __syncthreads();
        }
        if (!tid) g_tok[b] = si[0];
    }
}

__global__ __launch_bounds__(1024, 1) void decoder_kernel(
    const float* __restrict__ embed,
    const float* __restrict__ dWih0, const float* __restrict__ dbih0,
    const float* __restrict__ dWhh0, const float* __restrict__ dbhh0,
    const float* __restrict__ dWih1, const float* __restrict__ dbih1,
    const float* __restrict__ dWhh1, const float* __restrict__ dbhh1,
    const float* __restrict__ Wq, const float* __restrict__ bq,
    const float* __restrict__ Wc, const float* __restrict__ bc,
    const float* __restrict__ Wfc, const float* __restrict__ bfc,
    float* __restrict__ out)
{
    extern __shared__ __align__(16) ULL dsm[];
    __shared__ int toks[B];
    const size_t HID_OFF = (size_t)B * TGT * V;
    const size_t ATTN_OFF = HID_OFF + (size_t)2 * BH;

    for (int s = 0; s < TGT; s++) {
        if (threadIdx.x < B) toks[threadIdx.x] = s ? g_tok[threadIdx.x] : 0;
        __syncthreads();
        const float* h0in = s ? (g_dh0 + (size_t)((s - 1) & 1) * BH) : (g_h0seq + (size_t)(TIN - 1) * BH);
        const float* h1in = s ? (g_dh1 + (size_t)((s - 1) & 1) * BH) : (g_enc + (size_t)(TIN - 1) * BH);
        float* h0out = g_dh0 + (size_t)(s & 1) * BH;
        float* h1out = g_dh1 + (size_t)(s & 1) * BH;

        dec_gru_1024(embed, H, toks, dWih0, dbih0, h0in, dWhh0, dbhh0, h0out, nullptr, dsm);
        grid_sync();
        dec_gru_1024(h0out, H, nullptr, dWih1, dbih1, h1in, dWhh1, dbhh1, h1out, g_cat, dsm);
        grid_sync();
        lin_1024(Wq, H, bq, h1out, H, H, g_q, dsm);
        grid_sync();
        attn_1024(g_q, g_enc, g_cat, out + ATTN_OFF, s, (float*)dsm);
        grid_sync();
        lin_1024(Wc, 2 * H, bc, g_cat, 2 * H, 2 * H, g_comb, dsm);
        grid_sync();
        fc_1024(g_comb, Wfc, bfc, out, s, dsm);
        grid_sync();
        argmax_1024(out, s, (float*)dsm);
        grid_sync();
    }
    const float* f0 = g_dh0 + (size_t)((TGT - 1) & 1) * BH;
    const float* f1 = g_dh1 + (size_t)((TGT - 1) & 1) * BH;
    for (size_t i = (size_t)blockIdx.x * 1024 + threadIdx.x; i < (size_t)BH;
         i += (size_t)gridDim.x * 1024) {
        out[HID_OFF + i] = f0[i];
        out[HID_OFF + BH + i] = f1[i];
    }
}

extern "C" void kernel_launch(void* const* d_in, const int* in_sizes, int n_in,
                              void* d_out_, int out_size) {
    const float* x      = (const float*)d_in[0];
    const float* embed  = (const float*)d_in[1];
    const float* eWih0  = (const float*)d_in[2];
    const float* eWhh0  = (const float*)d_in[3];
    const float* ebih0  = (const float*)d_in[4];
    const float* ebhh0  = (const float*)d_in[5];
    const float* eWih1  = (const float*)d_in[6];
    const float* eWhh1  = (const float*)d_in[7];
    const float* ebih1  = (const float*)d_in[8];
    const float* ebhh1  = (const float*)d_in[9];
    const float* dWih0  = (const float*)d_in[10];
    const float* dWhh0  = (const float*)d_in[11];
    const float* dbih0  = (const float*)d_in[12];
    const float* dbhh0  = (const float*)d_in[13];
    const float* dWih1  = (const float*)d_in[14];
    const float* dWhh1  = (const float*)d_in[15];
    const float* dbih1  = (const float*)d_in[16];
    const float* dbhh1  = (const float*)d_in[17];
    const float* Wq     = (const float*)d_in[18];
    const float* bq     = (const float*)d_in[19];
    const float* Wc     = (const float*)d_in[20];
    const float* bc     = (const float*)d_in[21];
    const float* Wfc    = (const float*)d_in[22];
    const float* bfc    = (const float*)d_in[23];
    float* out = (float*)d_out_;

    float *gi0, *gi1, *h0seq, *enc;
    cudaGetSymbolAddress((void**)&gi0,   g_gi0);
    cudaGetSymbolAddress((void**)&gi1,   g_gi1);
    cudaGetSymbolAddress((void**)&h0seq, g_h0seq);
    cudaGetSymbolAddress((void**)&enc,   g_enc);

    const int ENC_SMEM = (24 * WS_PITCH + 64 * XS_PITCH) * (int)sizeof(float);
    cudaFuncSetAttribute(enc_recur_kernel, cudaFuncAttributeMaxDynamicSharedMemorySize, ENC_SMEM);
    const int DEC_SMEM = DSM_ULL * (int)sizeof(ULL);   // 80,256 B
    cudaFuncSetAttribute(decoder_kernel, cudaFuncAttributeMaxDynamicSharedMemorySize, DEC_SMEM);

    // 1) gi0 = X @ eWih0^T + ebih0
    gemm2_tn<<<dim3(H3/128, (B*TIN)/64), 256>>>(x, eWih0, ebih0, gi0, F, F, F, H3);
    // 2) encoder layer 0 recurrence
    enc_recur_kernel<<<128, 256, ENC_SMEM>>>(
        gi0, (long long)H3, (long long)TIN * H3, eWhh0, ebhh0, h0seq);
    // 3) gi1 = H0seq @ eWih1^T + ebih1
    gemm2_tn<<<dim3(H3/128, (B*TIN)/64), 256>>>(h0seq, eWih1, ebih1, gi1, H, H, H, H3);
    // 4) encoder layer 1 recurrence
    enc_recur_kernel<<<128, 256, ENC_SMEM>>>(
        gi1, (long long)B * H3, (long long)H3, eWhh1, ebhh1, enc);
    // 5) full autoregressive decoder (128 blocks x 1024 threads)
    decoder_kernel<<<128, 1024, DEC_SMEM>>>(
        embed, dWih0, dbih0, dWhh0, dbhh0, dWih1, dbih1, dWhh1, dbhh1,
        Wq, bq, Wc, bc, Wfc, bfc, out);
}

// round 6
// speedup vs baseline: 1.5281x; 1.0987x over previous
#include <cuda_runtime.h>
#include <cfloat>
#include <cstddef>

#define B 64
#define TIN 256
#define F 64
#define H 1024
#define H3 3072
#define TGT 64
#define V 32000
#define BH (B*H)

typedef unsigned long long ULL;
typedef unsigned int uint;

__device__ float g_gi0[(size_t)TIN * B * H3];
__device__ float g_gi1[(size_t)TIN * B * H3];
__device__ float g_h0seq[(size_t)TIN * BH];
__device__ float g_enc[(size_t)TIN * BH];
__device__ float g_dh0[2 * BH];
__device__ float g_dh1[2 * BH];
__device__ float g_q[BH];
__device__ float g_cat[B * 2 * H];
__device__ float g_comb[BH];
__device__ ULL   g_keys[B];
__device__ unsigned long long g_bar64;   // encoder-only grid barrier

__device__ __forceinline__ void grid_sync() {
    __syncthreads();
    if (threadIdx.x == 0) {
        __threadfence();
        unsigned long long old = atomicAdd(&g_bar64, 1ULL);
        unsigned gen = (unsigned)(old >> 32);
        if ((unsigned)old == gridDim.x - 1) {
            atomicAdd(&g_bar64, (1ULL << 32) - (unsigned long long)gridDim.x);
        } else {
            while ((unsigned)((*(volatile unsigned long long*)&g_bar64) >> 32) == gen) { }
        }
        __threadfence();
    }
    __syncthreads();
}

__device__ __forceinline__ float sigmoidf_(float x) { return 1.f / (1.f + expf(-x)); }
__device__ __forceinline__ void fma2(ULL& d, ULL a, ULL b) {
    asm("fma.rn.f32x2 %0, %1, %2, %0;" : "+l"(d) : "l"(a), "l"(b));
}
__device__ __forceinline__ float2 unpack2(ULL v) {
    float2 r; asm("mov.b64 {%0, %1}, %2;" : "=f"(r.x), "=f"(r.y) : "l"(v)); return r;
}
// total-order float key (matches '>' for non-NaN); monotone in value
__device__ __forceinline__ uint ord32(float f) {
    uint u = __float_as_uint(f);
    return u ^ ((u >> 31) ? 0xFFFFFFFFu : 0x80000000u);
}

// ============ FMA2 GEMM (bitwise-proven): C = A @ W^T + bias, tile 64x128 ============
__global__ __launch_bounds__(256) void gemm2_tn(
    const float* __restrict__ A, const float* __restrict__ W,
    const float* __restrict__ bias, float* __restrict__ C,
    int K, int lda, int ldw, int ldc)
{
    __shared__ __align__(16) ULL smu2[2 * 64 * 33];
    ULL* As2 = smu2;
    ULL* Ws2 = smu2 + 64 * 33;
    const int tid = threadIdx.x;
    const int tx = tid & 15, ty = tid >> 4;
    const int m0 = blockIdx.y * 64, n0 = blockIdx.x * 128;

    ULL acc[4][4];
#pragma unroll
    for (int r = 0; r < 4; r++)
#pragma unroll
        for (int q = 0; q < 4; q++) acc[r][q] = 0ULL;

    for (int k0 = 0; k0 < K; k0 += 32) {
        for (int i = tid; i < 2048; i += 256) {
            int m = i >> 5, k = i & 31;
            float v = A[(size_t)(m0 + m) * lda + k0 + k];
            ((float2*)As2)[m * 33 + k] = make_float2(v, v);
        }
        for (int i = tid; i < 2048; i += 256) {
            int pc = i >> 5, k = i & 31;
            int n_lo = n0 + (pc >> 4) * 32 + (pc & 15);
            ((float2*)Ws2)[pc * 33 + k] = make_float2(
                W[(size_t)n_lo * ldw + k0 + k], W[(size_t)(n_lo + 16) * ldw + k0 + k]);
        }
        __syncthreads();
#pragma unroll 8
        for (int k = 0; k < 32; k++) {
            ULL a0 = As2[ty * 33 + k], a1 = As2[(ty + 16) * 33 + k];
            ULL a2 = As2[(ty + 32) * 33 + k], a3 = As2[(ty + 48) * 33 + k];
            ULL w0 = Ws2[tx * 33 + k], w1 = Ws2[(16 + tx) * 33 + k];
            ULL w2 = Ws2[(32 + tx) * 33 + k], w3 = Ws2[(48 + tx) * 33 + k];
            fma2(acc[0][0], w0, a0); fma2(acc[0][1], w1, a0); fma2(acc[0][2], w2, a0); fma2(acc[0][3], w3, a0);
            fma2(acc[1][0], w0, a1); fma2(acc[1][1], w1, a1); fma2(acc[1][2], w2, a1); fma2(acc[1][3], w3, a1);
            fma2(acc[2][0], w0, a2); fma2(acc[2][1], w1, a2); fma2(acc[2][2], w2, a2); fma2(acc[2][3], w3, a2);
            fma2(acc[3][0], w0, a3); fma2(acc[3][1], w1, a3); fma2(acc[3][2], w2, a3); fma2(acc[3][3], w3, a3);
        }
        __syncthreads();
    }
#pragma unroll
    for (int r = 0; r < 4; r++) {
        int m = m0 + ty + 16 * r;
#pragma unroll
        for (int q = 0; q < 4; q++) {
            float2 v = unpack2(acc[r][q]);
            int n_lo = n0 + q * 32 + tx;
            C[(size_t)m * ldc + n_lo]      = v.x + bias[n_lo];
            C[(size_t)m * ldc + n_lo + 16] = v.y + bias[n_lo + 16];
        }
    }
}

// ============ persistent encoder recurrence — unchanged (proven) ============
#define WS_PITCH 1028
#define XS_PITCH 68
__global__ __launch_bounds__(256, 1) void enc_recur_kernel(
    const float* __restrict__ gi, long long gi_t_stride, long long gi_b_stride,
    const float* __restrict__ Whh, const float* __restrict__ bhh,
    float* __restrict__ hseq)
{
    extern __shared__ float sm[];
    float* ws = sm;
    float* xs = sm + 24 * WS_PITCH;

    const int tid = threadIdx.x;
    const int c = tid & 7, bq = tid >> 3;
    const int jb = blockIdx.x * 8;
    const int b0 = 2 * bq, b1 = b0 + 1;
    const int j = jb + c;

    for (int i = tid; i < 24 * 256; i += 256) {
        int r = i >> 8, kg = i & 255;
        int wr = (r >> 3) * H + jb + (r & 7);
        *(float4*)(ws + r * WS_PITCH + kg * 4) =
            *(const float4*)(Whh + (size_t)wr * H + kg * 4);
    }
    const float br = bhh[j], bz = bhh[H + j], bn = bhh[2 * H + j];
    __syncthreads();

    for (int t = 0; t < TIN; t++) {
        float ar0 = 0.f, ar1 = 0.f, az0 = 0.f, az1 = 0.f, an0 = 0.f, an1 = 0.f;
        const float* hprev = hseq + (size_t)(t - 1) * BH;
        if (t > 0) {
            for (int k0 = 0; k0 < H; k0 += 64) {
                for (int i = tid; i < 1024; i += 256) {
                    int b = i >> 4, kg = i & 15;
                    *(float4*)(xs + b * XS_PITCH + kg * 4) =
                        *(const float4*)(hprev + (size_t)b * H + k0 + kg * 4);
                }
                __syncthreads();
#pragma unroll
                for (int kk = 0; kk < 64; kk += 4) {
                    float4 x0 = *(const float4*)(xs + b0 * XS_PITCH + kk);
                    float4 x1 = *(const float4*)(xs + b1 * XS_PITCH + kk);
                    float4 w0 = *(const float4*)(ws + c * WS_PITCH + k0 + kk);
                    float4 w1 = *(const float4*)(ws + (8 + c) * WS_PITCH + k0 + kk);
                    float4 w2 = *(const float4*)(ws + (16 + c) * WS_PITCH + k0 + kk);
                    ar0 = fmaf(w0.x, x0.x, ar0); ar0 = fmaf(w0.y, x0.y, ar0);
                    ar0 = fmaf(w0.z, x0.z, ar0); ar0 = fmaf(w0.w, x0.w, ar0);
                    ar1 = fmaf(w0.x, x1.x, ar1); ar1 = fmaf(w0.y, x1.y, ar1);
                    ar1 = fmaf(w0.z, x1.z, ar1); ar1 = fmaf(w0.w, x1.w, ar1);
                    az0 = fmaf(w1.x, x0.x, az0); az0 = fmaf(w1.y, x0.y, az0);
                    az0 = fmaf(w1.z, x0.z, az0); az0 = fmaf(w1.w, x0.w, az0);
                    az1 = fmaf(w1.x, x1.x, az1); az1 = fmaf(w1.y, x1.y, az1);
                    az1 = fmaf(w1.z, x1.z, az1); az1 = fmaf(w1.w, x1.w, az1);
                    an0 = fmaf(w2.x, x0.x, an0); an0 = fmaf(w2.y, x0.y, an0);
                    an0 = fmaf(w2.z, x0.z, an0); an0 = fmaf(w2.w, x0.w, an0);
                    an1 = fmaf(w2.x, x1.x, an1); an1 = fmaf(w2.y, x1.y, an1);
                    an1 = fmaf(w2.z, x1.z, an1); an1 = fmaf(w2.w, x1.w, an1);
                }
                __syncthreads();
            }
        }
        const float* gr0 = gi + (size_t)b0 * gi_b_stride + (size_t)t * gi_t_stride;
        const float* gr1 = gi + (size_t)b1 * gi_b_stride + (size_t)t * gi_t_stride;
        float* hout = hseq + (size_t)t * BH;
        float hp0 = (t > 0) ? hprev[(size_t)b0 * H + j] : 0.f;
        float hp1 = (t > 0) ? hprev[(size_t)b1 * H + j] : 0.f;
        {
            float r = sigmoidf_(gr0[j] + ar0 + br);
            float z = sigmoidf_(gr0[H + j] + az0 + bz);
            float n = tanhf(gr0[2 * H + j] + r * (an0 + bn));
            hout[(size_t)b0 * H + j] = (1.f - z) * n + z * hp0;
        }
        {
            float r = sigmoidf_(gr1[j] + ar1 + br);
            float z = sigmoidf_(gr1[H + j] + az1 + bz);
            float n = tanhf(gr1[2 * H + j] + r * (an1 + bn));
            hout[(size_t)b1 * H + j] = (1.f - z) * n + z * hp1;
        }
        grid_sync();
    }
}

// ================= decoder phase kernels (one launch per phase per step) =================

// GRU cell: grid 256 blocks x 256 thr; block owns 4 cols (jb = blk*4); thread = (col c, batch b);
// computes 6 whole k-ascending chains (ih r/z/n + hh r/z/n) -> bitwise-identical epilogue.
__global__ __launch_bounds__(256) void dec_gru(
    const float* __restrict__ x, int xstride, int use_tok, int s,
    const float* __restrict__ Wih, const float* __restrict__ bih,
    const float* __restrict__ hin,
    const float* __restrict__ Whh, const float* __restrict__ bhh,
    float* __restrict__ hout, float* __restrict__ cat_aux)
{
    __shared__ float xs[64 * XS_PITCH];
    __shared__ float hs[64 * XS_PITCH];
    __shared__ float wi[12 * XS_PITCH];
    __shared__ float wh[12 * XS_PITCH];
    __shared__ int toks[B];
    const int tid = threadIdx.x;
    const int c = tid & 3, b = tid >> 2;
    const int jb = blockIdx.x * 4;
    const int j = jb + c;

    if (use_tok && tid < B)
        toks[tid] = (s == 0) ? 0 : (V - 1 - (int)(g_keys[tid] & 0x7FFFULL));
    __syncthreads();

    float air = 0.f, aiz = 0.f, ain = 0.f, ahr = 0.f, ahz = 0.f, ahn = 0.f;

    for (int k0 = 0; k0 < H; k0 += 64) {
        for (int i = tid; i < 1024; i += 256) {
            int bb = i >> 4, kg = i & 15;
            const float* xr = use_tok ? (x + (size_t)toks[bb] * xstride)
                                      : (x + (size_t)bb * xstride);
            *(float4*)(xs + bb * XS_PITCH + kg * 4) = *(const float4*)(xr + k0 + kg * 4);
            *(float4*)(hs + bb * XS_PITCH + kg * 4) =
                *(const float4*)(hin + (size_t)bb * H + k0 + kg * 4);
        }
        if (tid < 192) {
            int r = tid >> 4, kg = tid & 15;
            int wr = (r >> 2) * H + jb + (r & 3);
            *(float4*)(wi + r * XS_PITCH + kg * 4) = *(const float4*)(Wih + (size_t)wr * H + k0 + kg * 4);
            *(float4*)(wh + r * XS_PITCH + kg * 4) = *(const float4*)(Whh + (size_t)wr * H + k0 + kg * 4);
        }
        __syncthreads();
#pragma unroll
        for (int kk = 0; kk < 64; kk += 4) {
            float4 xv = *(const float4*)(xs + b * XS_PITCH + kk);
            float4 hv = *(const float4*)(hs + b * XS_PITCH + kk);
            float4 wir = *(const float4*)(wi + c * XS_PITCH + kk);
            float4 wiz = *(const float4*)(wi + (4 + c) * XS_PITCH + kk);
            float4 win = *(const float4*)(wi + (8 + c) * XS_PITCH + kk);
            float4 whr = *(const float4*)(wh + c * XS_PITCH + kk);
            float4 whz = *(const float4*)(wh + (4 + c) * XS_PITCH + kk);
            float4 whn = *(const float4*)(wh + (8 + c) * XS_PITCH + kk);
            air = fmaf(wir.x, xv.x, air); air = fmaf(wir.y, xv.y, air);
            air = fmaf(wir.z, xv.z, air); air = fmaf(wir.w, xv.w, air);
            aiz = fmaf(wiz.x, xv.x, aiz); aiz = fmaf(wiz.y, xv.y, aiz);
            aiz = fmaf(wiz.z, xv.z, aiz); aiz = fmaf(wiz.w, xv.w, aiz);
            ain = fmaf(win.x, xv.x, ain); ain = fmaf(win.y, xv.y, ain);
            ain = fmaf(win.z, xv.z, ain); ain = fmaf(win.w, xv.w, ain);
            ahr = fmaf(whr.x, hv.x, ahr); ahr = fmaf(whr.y, hv.y, ahr);
            ahr = fmaf(whr.z, hv.z, ahr); ahr = fmaf(whr.w, hv.w, ahr);
            ahz = fmaf(whz.x, hv.x, ahz); ahz = fmaf(whz.y, hv.y, ahz);
            ahz = fmaf(whz.z, hv.z, ahz); ahz = fmaf(whz.w, hv.w, ahz);
            ahn = fmaf(whn.x, hv.x, ahn); ahn = fmaf(whn.y, hv.y, ahn);
            ahn = fmaf(whn.z, hv.z, ahn); ahn = fmaf(whn.w, hv.w, ahn);
        }
        __syncthreads();
    }
    float hp = hin[(size_t)b * H + j];
    float r = sigmoidf_((air + bih[j]) + (ahr + bhh[j]));
    float z = sigmoidf_((aiz + bih[H + j]) + (ahz + bhh[H + j]));
    float n = tanhf((ain + bih[2 * H + j]) + r * (ahn + bhh[2 * H + j]));
    float h = (1.f - z) * n + z * hp;
    hout[(size_t)b * H + j] = h;
    if (cat_aux) cat_aux[(size_t)b * 2 * H + H + j] = h;
}

// Linear: Y[b][jb+c] = X[b] . Wt[jb+c] + bias; grid 256 x 256; 1 whole chain / thread.
__global__ __launch_bounds__(256) void lin_kernel(
    const float* __restrict__ Wt, int wstride, const float* __restrict__ bias,
    const float* __restrict__ X, int xstride, int K, float* __restrict__ Y,
    int reset_keys)
{
    __shared__ float xs[64 * XS_PITCH];
    __shared__ float ws[4 * XS_PITCH];
    const int tid = threadIdx.x;
    const int c = tid & 3, b = tid >> 2;
    const int jb = blockIdx.x * 4;
    if (reset_keys && blockIdx.x == 0 && tid < B) g_keys[tid] = 0ULL;

    float a = 0.f;
    for (int k0 = 0; k0 < K; k0 += 64) {
        for (int i = tid; i < 1024; i += 256) {
            int bb = i >> 4, kg = i & 15;
            *(float4*)(xs + bb * XS_PITCH + kg * 4) =
                *(const float4*)(X + (size_t)bb * xstride + k0 + kg * 4);
        }
        if (tid < 64) {
            int r = tid >> 4, kg = tid & 15;
            *(float4*)(ws + r * XS_PITCH + kg * 4) =
                *(const float4*)(Wt + (size_t)(jb + r) * wstride + k0 + kg * 4);
        }
        __syncthreads();
#pragma unroll
        for (int kk = 0; kk < 64; kk += 4) {
            float4 xv = *(const float4*)(xs + b * XS_PITCH + kk);
            float4 wv = *(const float4*)(ws + c * XS_PITCH + kk);
            a = fmaf(wv.x, xv.x, a); a = fmaf(wv.y, xv.y, a);
            a = fmaf(wv.z, xv.z, a); a = fmaf(wv.w, xv.w, a);
        }
        __syncthreads();
    }
    Y[(size_t)b * H + jb + c] = a + bias[jb + c];
}

// attention: grid 64 blocks x 1024 threads (math identical to R5)
__global__ __launch_bounds__(1024) void attn_kernel(
    const float* __restrict__ q, const float* __restrict__ enc,
    float* __restrict__ cat, float* __restrict__ attn_out, int s)
{
    __shared__ float qs[H];
    __shared__ float wv[TIN];
    __shared__ float red[256];
    const int b = blockIdx.x, tid = threadIdx.x;
    qs[tid] = q[(size_t)b * H + tid];
    __syncthreads();
    const int warp = tid >> 5, lane = tid & 31;
    for (int t = warp; t < TIN; t += 32) {
        const float* e = enc + (size_t)(t * B + b) * H;
        float sacc = 0.f;
#pragma unroll 4
        for (int k = lane; k < H; k += 32) sacc = fmaf(qs[k], e[k], sacc);
        for (int o = 16; o; o >>= 1) sacc += __shfl_xor_sync(0xffffffffu, sacc, o);
        if (!lane) wv[t] = sacc;
    }
    __syncthreads();
    float v = 0.f, ev = 0.f;
    if (tid < 256) { v = wv[tid]; red[tid] = v; }
    __syncthreads();
    for (int st = 128; st; st >>= 1) { if (tid < st) red[tid] = fmaxf(red[tid], red[tid + st]); __syncthreads(); }
    float mx = red[0]; __syncthreads();
    if (tid < 256) { ev = expf(v - mx); red[tid] = ev; }
    __syncthreads();
    for (int st = 128; st; st >>= 1) { if (tid < st) red[tid] += red[tid + st]; __syncthreads(); }
    if (tid < 256) {
        float aw = ev / red[0];
        wv[tid] = aw;
        attn_out[((size_t)b * TIN + tid) * TGT + s] = aw;
    }
    __syncthreads();
    {
        int k = tid;
        float sacc = 0.f;
        for (int t = 0; t < TIN; t++) sacc = fmaf(wv[t], enc[(size_t)(t * B + b) * H + k], sacc);
        cat[(size_t)b * 2 * H + k] = sacc;
    }
}

// fc + fused argmax: grid 500 blocks x 256 thr; tile 64m x 64n; scalar fmaf chains.
__global__ __launch_bounds__(256) void fc_argmax(
    const float* __restrict__ A, const float* __restrict__ Wfc,
    const float* __restrict__ bfc, float* __restrict__ out, int s)
{
    __shared__ float As[32][65];
    __shared__ float Ws[32][65];
    __shared__ ULL skeys[B];
    const int tid = threadIdx.x;
    const int tx = tid & 15, ty = tid >> 4;
    const int n0 = blockIdx.x * 64;
    if (tid < B) skeys[tid] = 0ULL;

    float acc[4][4];
#pragma unroll
    for (int i = 0; i < 4; i++)
#pragma unroll
        for (int jj = 0; jj < 4; jj++) acc[i][jj] = 0.f;

    for (int k0 = 0; k0 < H; k0 += 32) {
        for (int i = tid; i < 2048; i += 256) {
            int m = i >> 5, k = i & 31;
            As[k][m] = A[(size_t)m * H + k0 + k];
        }
        for (int i = tid; i < 2048; i += 256) {
            int n = i >> 5, k = i & 31;
            Ws[k][n] = Wfc[(size_t)(n0 + n) * H + k0 + k];
        }
        __syncthreads();
#pragma unroll
        for (int k = 0; k < 32; k++) {
            float av[4], wv[4];
#pragma unroll
            for (int i = 0; i < 4; i++) av[i] = As[k][ty + 16 * i];
#pragma unroll
            for (int jj = 0; jj < 4; jj++) wv[jj] = Ws[k][tx + 16 * jj];
#pragma unroll
            for (int i = 0; i < 4; i++)
#pragma unroll
                for (int jj = 0; jj < 4; jj++) acc[i][jj] = fmaf(av[i], wv[jj], acc[i][jj]);
        }
        __syncthreads();
    }
#pragma unroll
    for (int i = 0; i < 4; i++) {
        int m = ty + 16 * i;
        ULL rowmax = 0ULL;
#pragma unroll
        for (int jj = 0; jj < 4; jj++) {
            int n = n0 + tx + 16 * jj;
            float vo = acc[i][jj] + bfc[n];
            out[((size_t)m * TGT + s) * V + n] = vo;
            ULL key = ((ULL)ord32(vo) << 15) | (ULL)(V - 1 - n);
            if (key > rowmax) rowmax = key;
        }
        atomicMax(&skeys[m], rowmax);
    }
    __syncthreads();
    if (tid < B) atomicMax(&g_keys[tid], skeys[tid]);
}

// ================== host orchestration: ~390 graph nodes ==================
extern "C" void kernel_launch(void* const* d_in, const int* in_sizes, int n_in,
                              void* d_out_, int out_size) {
    const float* x      = (const float*)d_in[0];
    const float* embed  = (const float*)d_in[1];
    const float* eWih0  = (const float*)d_in[2];
    const float* eWhh0  = (const float*)d_in[3];
    const float* ebih0  = (const float*)d_in[4];
    const float* ebhh0  = (const float*)d_in[5];
    const float* eWih1  = (const float*)d_in[6];
    const float* eWhh1  = (const float*)d_in[7];
    const float* ebih1  = (const float*)d_in[8];
    const float* ebhh1  = (const float*)d_in[9];
    const float* dWih0  = (const float*)d_in[10];
    const float* dWhh0  = (const float*)d_in[11];
    const float* dbih0  = (const float*)d_in[12];
    const float* dbhh0  = (const float*)d_in[13];
    const float* dWih1  = (const float*)d_in[14];
    const float* dWhh1  = (const float*)d_in[15];
    const float* dbih1  = (const float*)d_in[16];
    const float* dbhh1  = (const float*)d_in[17];
    const float* Wq     = (const float*)d_in[18];
    const float* bq     = (const float*)d_in[19];
    const float* Wc     = (const float*)d_in[20];
    const float* bc     = (const float*)d_in[21];
    const float* Wfc    = (const float*)d_in[22];
    const float* bfc    = (const float*)d_in[23];
    float* out = (float*)d_out_;

    const size_t HID_OFF  = (size_t)B * TGT * V;
    const size_t ATTN_OFF = HID_OFF + (size_t)2 * BH;

    float *gi0, *gi1, *h0seq, *enc, *dh0, *dh1, *q, *cat, *comb;
    cudaGetSymbolAddress((void**)&gi0,   g_gi0);
    cudaGetSymbolAddress((void**)&gi1,   g_gi1);
    cudaGetSymbolAddress((void**)&h0seq, g_h0seq);
    cudaGetSymbolAddress((void**)&enc,   g_enc);
    cudaGetSymbolAddress((void**)&dh0,   g_dh0);
    cudaGetSymbolAddress((void**)&dh1,   g_dh1);
    cudaGetSymbolAddress((void**)&q,     g_q);
    cudaGetSymbolAddress((void**)&cat,   g_cat);
    cudaGetSymbolAddress((void**)&comb,  g_comb);

    const int ENC_SMEM = (24 * WS_PITCH + 64 * XS_PITCH) * (int)sizeof(float);
    cudaFuncSetAttribute(enc_recur_kernel, cudaFuncAttributeMaxDynamicSharedMemorySize, ENC_SMEM);

    // ---- encoder ----
    gemm2_tn<<<dim3(H3/128, (B*TIN)/64), 256>>>(x, eWih0, ebih0, gi0, F, F, F, H3);
    enc_recur_kernel<<<128, 256, ENC_SMEM>>>(
        gi0, (long long)H3, (long long)TIN * H3, eWhh0, ebhh0, h0seq);
    gemm2_tn<<<dim3(H3/128, (B*TIN)/64), 256>>>(h0seq, eWih1, ebih1, gi1, H, H, H, H3);
    enc_recur_kernel<<<128, 256, ENC_SMEM>>>(
        gi1, (long long)B * H3, (long long)H3, eWhh1, ebhh1, enc);

    // ---- decoder: 6 kernels per step ----
    for (int s = 0; s < TGT; s++) {
        const float* h0in = s ? (dh0 + (size_t)((s - 1) & 1) * BH) : (h0seq + (size_t)(TIN - 1) * BH);
        const float* h1in = s ? (dh1 + (size_t)((s - 1) & 1) * BH) : (enc + (size_t)(TIN - 1) * BH);
        float* h0out = dh0 + (size_t)(s & 1) * BH;
        float* h1out = dh1 + (size_t)(s & 1) * BH;

        dec_gru<<<256, 256>>>(embed, H, 1, s, dWih0, dbih0, h0in, dWhh0, dbhh0, h0out, nullptr);
        dec_gru<<<256, 256>>>(h0out, H, 0, s, dWih1, dbih1, h1in, dWhh1, dbhh1, h1out, cat);
        lin_kernel<<<256, 256>>>(Wq, H, bq, h1out, H, H, q, 0);
        attn_kernel<<<B, 1024>>>(q, enc, cat, out + ATTN_OFF, s);
        lin_kernel<<<256, 256>>>(Wc, 2 * H, bc, cat, 2 * H, 2 * H, comb, 1);  // also resets g_keys
        fc_argmax<<<V / 64, 256>>>(comb, Wfc, bfc, out, s);
    }

    // ---- final hidden [2,B,H]: decoder (h0,h1) after step TGT-1 (parity 1) ----
    cudaMemcpyAsync(out + HID_OFF,      dh0 + BH, (size_t)BH * sizeof(float), cudaMemcpyDeviceToDevice);
    cudaMemcpyAsync(out + HID_OFF + BH, dh1 + BH, (size_t)BH * sizeof(float), cudaMemcpyDeviceToDevice);
}